// round 12
// baseline (speedup 1.0000x reference)
#include <cuda_runtime.h>
#include <math.h>

// Problem constants
constexpr int FH   = 96;
constexpr int FW   = 96;
constexpr int FC   = 512;
constexpr int FB   = 16;
constexpr int NROI = 32;
constexpr int NREG = 50;          // 1 + 4 + 9 + 36
constexpr int C4   = FC / 4;      // 128 float4 channels
constexpr int RS   = FW * C4;     // row stride in float4 units
constexpr int NCK  = 12;          // 8-row chunks over [0,96)

// Region table: per (roi, region) -> x1, x2, y1, y2
__device__ int4 d_regions[NROI * NREG];

// ---------------------------------------------------------------------------
// Prep: init ALL 50 regions of every (b,roi) to -inf bits AND compute the
// exact Python-double region boundaries (verified math, unchanged since R1).
// ---------------------------------------------------------------------------
__global__ void prep_kernel(const int* __restrict__ rois,
                            unsigned int* __restrict__ out) {
    int gid = blockIdx.x * blockDim.x + threadIdx.x;

    if (gid < FB * NROI * NREG * 128) {           // uint4 index over whole out
        ((uint4*)out)[gid] =
            make_uint4(0xFF800000u, 0xFF800000u, 0xFF800000u, 0xFF800000u);
    }

    if (gid >= NROI * NREG) return;
    int roi = gid / NREG;
    int k   = gid % NREG;

    int P, off;
    if      (k < 1)  { P = 1; off = 0; }
    else if (k < 5)  { P = 2; off = 1; }
    else if (k < 14) { P = 3; off = 5; }
    else             { P = 6; off = 14; }
    int idx = k - off;
    int ix  = idx / P;
    int jy  = idx % P;

    double x = (double)rois[roi * 4 + 0];
    double y = (double)rois[roi * 4 + 1];
    double w = (double)rois[roi * 4 + 2];
    double h = (double)rois[roi * 4 + 3];

    double cl = h / (double)P;   // x-axis step (reference quirk)
    double rl = w / (double)P;   // y-axis step

    double tx = __dadd_rn(x, __dmul_rn((double)ix, cl));
    int x1 = (int)rint(tx);
    int x2 = (int)rint(__dadd_rn(tx, cl));

    double ty = __dadd_rn(y, __dmul_rn((double)jy, rl));
    int y1 = (int)rint(ty);
    int y2 = (int)rint(__dadd_rn(ty, rl));

    x1 = max(0, min(FW, x1));
    x2 = max(0, min(FW, x2));
    y1 = max(0, min(FH, y1));
    y2 = max(0, min(FH, y2));

    d_regions[roi * NREG + k] = make_int4(x1, x2, y1, y2);
}

// Sign-split float atomic max on raw bits (proven rel_err=0 in R6-R11).
__device__ __forceinline__ void atomicMaxFloat(float* addr, float v) {
    if (v >= 0.0f) atomicMax((int*)addr, __float_as_int(v));
    else           atomicMin((unsigned int*)addr, __float_as_uint(v));
}

__device__ __forceinline__ void vmax4(float4& a, const float4 b) {
    a.x = fmaxf(a.x, b.x);
    a.y = fmaxf(a.y, b.y);
    a.z = fmaxf(a.z, b.z);
    a.w = fmaxf(a.w, b.w);
}

__device__ __forceinline__ void atomic4(float* o, const float4 a) {
    atomicMaxFloat(o + 0, a.x);
    atomicMaxFloat(o + 1, a.y);
    atomicMaxFloat(o + 2, a.z);
    atomicMaxFloat(o + 3, a.w);
}

// ---------------------------------------------------------------------------
// One warp-group's level: P bands x P segments at region offset OFF.
// Walks chunk rows in 2-row steps, synced with the other groups via named
// barrier (bar.sync 1, 384) so the three levels re-hit the same rows in L1.
// Accumulators bound to the current band; flushed via atomics on band change
// (handles the +/-1 band jitter exactly: each band uses its own exact range).
// FOLD0: flushes also fold into region 0 (pool1; exact, validated since R7).
// ---------------------------------------------------------------------------
template <int P, int OFF, bool FOLD0>
__device__ __forceinline__ void group_run(const float4* __restrict__ fmb,
                                          const int4*  __restrict__ regs,
                                          float*       __restrict__ outb,
                                          int ck_lo, int ck_hi) {
    int sx1[P], sx2[P], by1[P], by2[P];
#pragma unroll
    for (int i = 0; i < P; i++) { int4 q = __ldg(&regs[OFF + i * P]); sx1[i] = q.x; sx2[i] = q.y; }
#pragma unroll
    for (int j = 0; j < P; j++) { int4 q = __ldg(&regs[OFF + j]);     by1[j] = q.z; by2[j] = q.w; }

    const float4 NEG = make_float4(-INFINITY, -INFINITY, -INFINITY, -INFINITY);
    float4 acc[P];
#pragma unroll
    for (int i = 0; i < P; i++) acc[i] = NEG;
    int ab = -1;                                  // band the acc currently holds

    for (int y0 = ck_lo; y0 < ck_hi; y0 += 2) {
#pragma unroll
        for (int j = 0; j < P; j++) {
            int ys = max(by1[j], y0);
            int ye = min(by2[j], y0 + 2);
            if (ys < ye) {
                if (j != ab) {                    // band transition: flush
                    if (ab >= 0) {
#pragma unroll
                        for (int i = 0; i < P; i++) {
                            float* o = outb + ((size_t)(OFF + i * P + ab) << 9);
                            atomic4(o, acc[i]);
                            if (FOLD0) atomic4(outb, acc[i]);
                            acc[i] = NEG;
                        }
                    }
                    ab = j;
                }
                // accumulate rows [ys, ye) for every segment
#pragma unroll
                for (int i = 0; i < P; i++) {
                    int x1 = sx1[i], x2 = sx2[i];
                    if (ye - ys == 2) {
                        const float4* r0 = fmb + (size_t)ys * RS;
                        const float4* r1 = r0 + RS;
                        float4 a0 = acc[i], a1 = NEG;
                        int x = x1;
                        for (; x + 2 <= x2; x += 2) {     // 4 loads in flight
                            float4 v0 = __ldg(r0 + (size_t)x * C4);
                            float4 v1 = __ldg(r1 + (size_t)x * C4);
                            float4 v2 = __ldg(r0 + (size_t)(x + 1) * C4);
                            float4 v3 = __ldg(r1 + (size_t)(x + 1) * C4);
                            vmax4(a0, v0); vmax4(a1, v1);
                            vmax4(a0, v2); vmax4(a1, v3);
                        }
                        if (x < x2) {
                            vmax4(a0, __ldg(r0 + (size_t)x * C4));
                            vmax4(a1, __ldg(r1 + (size_t)x * C4));
                        }
                        vmax4(a0, a1);
                        acc[i] = a0;
                    } else {
                        const float4* r0 = fmb + (size_t)ys * RS;
                        float4 a0 = acc[i], a1 = NEG;
                        int x = x1;
                        for (; x + 2 <= x2; x += 2) {
                            float4 v0 = __ldg(r0 + (size_t)x * C4);
                            float4 v1 = __ldg(r0 + (size_t)(x + 1) * C4);
                            vmax4(a0, v0); vmax4(a1, v1);
                        }
                        if (x < x2)
                            vmax4(a0, __ldg(r0 + (size_t)x * C4));
                        vmax4(a0, a1);
                        acc[i] = a0;
                    }
                }
            }
        }
        asm volatile("bar.sync 1, 384;" ::: "memory");   // row-align the 3 groups
    }

    if (ab >= 0) {                                 // final flush
#pragma unroll
        for (int i = 0; i < P; i++) {
            float* o = outb + ((size_t)(OFF + i * P + ab) << 9);
            atomic4(o, acc[i]);
            if (FOLD0) atomic4(outb, acc[i]);
        }
    }
}

// ---------------------------------------------------------------------------
// One block = (batch, roi, 8-row chunk). 384 threads = 3 warp-groups x 128
// channels; group 0 = pool6, 1 = pool3, 2 = pool2(+pool1 fold). Groups scan
// the same rows in lockstep -> 2nd/3rd group served from L1, L2 traffic ~1x.
// ---------------------------------------------------------------------------
__global__ void __launch_bounds__(384, 2)
roi_pool_fused3(const float* __restrict__ fm, float* __restrict__ out) {
    int bid = blockIdx.x;
    int ck  = bid % NCK;
    int rr  = bid / NCK;
    int roi = rr & 31;
    int b   = rr >> 5;

    int tid = threadIdx.x;
    int g   = tid >> 7;           // warp-group 0,1,2
    int c   = tid & 127;          // float4 channel

    const int4* regs = d_regions + roi * NREG;

    // Union y-range across levels (first band start, last band end per level)
    int ylo = min(min(__ldg(&regs[1]).z, __ldg(&regs[5]).z), __ldg(&regs[14]).z);
    int yhi = max(max(__ldg(&regs[2]).w, __ldg(&regs[7]).w), __ldg(&regs[19]).w);

    int ck_lo = ck * 8, ck_hi = ck_lo + 8;
    if (ck_lo >= yhi || ck_hi <= ylo) return;     // uniform early exit

    const float4* fmb  = (const float4*)fm + (size_t)b * FH * FW * C4 + c;
    float*        outb = out + (((size_t)(b * NROI + roi) * NREG) << 9) + c * 4;

    if (g == 0)      group_run<6, 14, false>(fmb, regs, outb, ck_lo, ck_hi);
    else if (g == 1) group_run<3, 5,  false>(fmb, regs, outb, ck_lo, ck_hi);
    else             group_run<2, 1,  true >(fmb, regs, outb, ck_lo, ck_hi);
}

extern "C" void kernel_launch(void* const* d_in, const int* in_sizes, int n_in,
                              void* d_out, int out_size) {
    const float* fm   = (const float*)d_in[0];
    const int*   rois = (const int*)d_in[1];
    float*       out  = (float*)d_out;

    int ninit4 = FB * NROI * NREG * 128;          // uint4 count, whole output
    prep_kernel<<<(ninit4 + 255) / 256, 256>>>(rois, (unsigned int*)out);
    roi_pool_fused3<<<FB * NROI * NCK, 384>>>(fm, out);
}

// round 13
// speedup vs baseline: 1.9227x; 1.9227x over previous
#include <cuda_runtime.h>
#include <math.h>

constexpr int FH   = 96;
constexpr int FW   = 96;
constexpr int FC   = 512;
constexpr int FB   = 16;
constexpr int NROI = 32;
constexpr int NREG = 50;          // 1 + 4 + 9 + 36
constexpr int C4   = FC / 4;      // 128 float4 channels
constexpr int RS   = FW * C4;     // row stride in float4 units
constexpr int CH   = 8;           // rows per chunk
constexpr int NCK  = FH / CH;     // 12

__device__ int4 d_regions[NROI * NREG];

// ---------------------------------------------------------------------------
// Prep: init ALL 50 regions to -inf bits + exact Python-double boundaries
// (verified math, unchanged since R1).
// ---------------------------------------------------------------------------
__global__ void prep_kernel(const int* __restrict__ rois,
                            unsigned int* __restrict__ out) {
    int gid = blockIdx.x * blockDim.x + threadIdx.x;

    if (gid < FB * NROI * NREG * 128) {
        ((uint4*)out)[gid] =
            make_uint4(0xFF800000u, 0xFF800000u, 0xFF800000u, 0xFF800000u);
    }

    if (gid >= NROI * NREG) return;
    int roi = gid / NREG;
    int k   = gid % NREG;

    int P, off;
    if      (k < 1)  { P = 1; off = 0; }
    else if (k < 5)  { P = 2; off = 1; }
    else if (k < 14) { P = 3; off = 5; }
    else             { P = 6; off = 14; }
    int idx = k - off;
    int ix  = idx / P;
    int jy  = idx % P;

    double x = (double)rois[roi * 4 + 0];
    double y = (double)rois[roi * 4 + 1];
    double w = (double)rois[roi * 4 + 2];
    double h = (double)rois[roi * 4 + 3];

    double cl = h / (double)P;   // x-axis step (reference quirk)
    double rl = w / (double)P;   // y-axis step

    double tx = __dadd_rn(x, __dmul_rn((double)ix, cl));
    int x1 = (int)rint(tx);
    int x2 = (int)rint(__dadd_rn(tx, cl));

    double ty = __dadd_rn(y, __dmul_rn((double)jy, rl));
    int y1 = (int)rint(ty);
    int y2 = (int)rint(__dadd_rn(ty, rl));

    x1 = max(0, min(FW, x1));
    x2 = max(0, min(FW, x2));
    y1 = max(0, min(FH, y1));
    y2 = max(0, min(FH, y2));

    d_regions[roi * NREG + k] = make_int4(x1, x2, y1, y2);
}

// Sign-split float atomic max on raw bits (proven rel_err=0 in R6-R12).
__device__ __forceinline__ void atomicMaxFloat(float* addr, float v) {
    if (v >= 0.0f) atomicMax((int*)addr, __float_as_int(v));
    else           atomicMin((unsigned int*)addr, __float_as_uint(v));
}

__device__ __forceinline__ void vmax4(float4& a, const float4 b) {
    a.x = fmaxf(a.x, b.x);
    a.y = fmaxf(a.y, b.y);
    a.z = fmaxf(a.z, b.z);
    a.w = fmaxf(a.w, b.w);
}

__device__ __forceinline__ void atomic4(float* o, const float4 a) {
    atomicMaxFloat(o + 0, a.x);
    atomicMaxFloat(o + 1, a.y);
    atomicMaxFloat(o + 2, a.z);
    atomicMaxFloat(o + 3, a.w);
}

#define NEG4 make_float4(-INFINITY, -INFINITY, -INFINITY, -INFINITY)

// ---------------------------------------------------------------------------
// Per-level state: walking band index with flush-on-advance; exact x-ranges
// per segment (packed x1|x2<<8, values < 97 fit). All acc/xr indices static
// (unrolled) so everything stays in registers.
// ---------------------------------------------------------------------------
template <int P, int OFF>
struct Level {
    int j, y1, y2, y1n;
    bool active;
    float4 acc[P];
    int xr[P];

    __device__ __forceinline__ void init(const int4* __restrict__ regs) {
        j = 0; active = false;
        int4 q = __ldg(&regs[OFF]);
        y1 = q.z; y2 = q.w;
        y1n = (P > 1) ? __ldg(&regs[OFF + 1]).z : (1 << 30);
#pragma unroll
        for (int i = 0; i < P; i++) {
            int4 r = __ldg(&regs[OFF + i * P]);
            xr[i] = r.x | (r.y << 8);
            acc[i] = NEG4;
        }
    }

    __device__ __forceinline__ void flush(float* __restrict__ outb) {
#pragma unroll
        for (int i = 0; i < P; i++) {
            atomic4(outb + ((size_t)(OFF + i * P + j) << 9), acc[i]);
            acc[i] = NEG4;
        }
        active = false;
    }

    __device__ __forceinline__ void walk(int y, const int4* __restrict__ regs,
                                         float* __restrict__ outb) {
        while (j < P && y >= y2) {
            if (active) flush(outb);
            j++;
            if (j < P) {
                int4 q = __ldg(&regs[OFF + j]);
                y1 = q.z; y2 = q.w;
                y1n = (j + 1 < P) ? __ldg(&regs[OFF + j + 1]).z : (1 << 30);
            }
        }
    }

    __device__ __forceinline__ void row(const float4* __restrict__ rowp) {
        active = true;
#pragma unroll
        for (int i = 0; i < P; i++) {
            int x1 = xr[i] & 0xff, x2 = xr[i] >> 8;
            float4 a0 = acc[i], a1 = NEG4, a2 = NEG4, a3 = NEG4;
            int x = x1;
            for (; x + 4 <= x2; x += 4) {         // 4 loads in flight
                float4 v0 = __ldg(rowp + (size_t)x * C4);
                float4 v1 = __ldg(rowp + (size_t)(x + 1) * C4);
                float4 v2 = __ldg(rowp + (size_t)(x + 2) * C4);
                float4 v3 = __ldg(rowp + (size_t)(x + 3) * C4);
                vmax4(a0, v0); vmax4(a1, v1); vmax4(a2, v2); vmax4(a3, v3);
            }
            if (x + 2 <= x2) {
                float4 v0 = __ldg(rowp + (size_t)x * C4);
                float4 v1 = __ldg(rowp + (size_t)(x + 1) * C4);
                vmax4(a0, v0); vmax4(a1, v1);
                x += 2;
            }
            if (x < x2) vmax4(a0, __ldg(rowp + (size_t)x * C4));
            vmax4(a0, a1); vmax4(a2, a3); vmax4(a0, a2);
            acc[i] = a0;
        }
    }

    // Rare fixup: row y also belongs to band j+1 (+/-1 jitter overlap).
    // Re-scan the (L1-hot) row with exact x-ranges, atomic into band j+1.
    __device__ __forceinline__ void rowOverlap(const float4* __restrict__ rowp,
                                               float* __restrict__ outb) {
        int jj = j + 1;
#pragma unroll
        for (int i = 0; i < P; i++) {
            int x1 = xr[i] & 0xff, x2 = xr[i] >> 8;
            float4 a0 = NEG4, a1 = NEG4;
            int x = x1;
            for (; x + 2 <= x2; x += 2) {
                float4 v0 = __ldg(rowp + (size_t)x * C4);
                float4 v1 = __ldg(rowp + (size_t)(x + 1) * C4);
                vmax4(a0, v0); vmax4(a1, v1);
            }
            if (x < x2) vmax4(a0, __ldg(rowp + (size_t)x * C4));
            vmax4(a0, a1);
            atomic4(outb + ((size_t)(OFF + i * P + jj) << 9), a0);
        }
    }
};

// ---------------------------------------------------------------------------
// Fused kernel: block = (b, roi, 8-row chunk), thread = float4 channel.
// Per row: pool2 pass (wide segments, takes the L2 miss with MLP 4), then
// pool3 and pool6 passes re-reading the same 32KB row from L1. No barriers.
// ---------------------------------------------------------------------------
__global__ void __launch_bounds__(128)
roi_pool_l1fused(const float* __restrict__ fm, float* __restrict__ out) {
    int bid = blockIdx.x;
    int ck  = bid % NCK;
    int rr  = bid / NCK;
    int roi = rr & 31;
    int b   = rr >> 5;            // batch slowest: blocks share one image in L2
    int c   = threadIdx.x;

    const int4* regs = d_regions + roi * NREG;

    int ylo = __ldg(&regs[0]).z;  // all levels start exactly at roi y
    // union bottom: last band end per level (bottom edges can jitter +/-1)
    int yhi = max(max(__ldg(&regs[2]).w, __ldg(&regs[7]).w), __ldg(&regs[19]).w);

    int row_lo = max(ylo, ck * CH);
    int row_hi = min(yhi, ck * CH + CH);
    if (row_lo >= row_hi) return;

    const float4* fmb  = (const float4*)fm + (size_t)b * FH * FW * C4 + c;
    float*        outb = out + (((size_t)(b * NROI + roi) * NREG) << 9) + c * 4;

    Level<2, 1>  l2; l2.init(regs);
    Level<3, 5>  l3; l3.init(regs);
    Level<6, 14> l6; l6.init(regs);

    // advance walkers to the chunk start (flushes nothing: inactive)
    l2.walk(row_lo, regs, outb);
    l3.walk(row_lo, regs, outb);
    l6.walk(row_lo, regs, outb);

    for (int y = row_lo; y < row_hi; y++) {
        l2.walk(y, regs, outb);
        l3.walk(y, regs, outb);
        l6.walk(y, regs, outb);

        const float4* rowp = fmb + (size_t)y * RS;

        if (l2.j < 2 && y >= l2.y1) l2.row(rowp);   // first touch: L2/DRAM
        if (l3.j < 3 && y >= l3.y1) l3.row(rowp);   // L1 hit
        if (l6.j < 6 && y >= l6.y1) l6.row(rowp);   // L1 hit

        // rare +/-1 jitter overlap rows (exact, double-count safe for max)
        if (y >= l2.y1n) l2.rowOverlap(rowp, outb);
        if (y >= l3.y1n) l3.rowOverlap(rowp, outb);
        if (y >= l6.y1n) l6.rowOverlap(rowp, outb);
    }

    if (l2.active) l2.flush(outb);
    if (l3.active) l3.flush(outb);
    if (l6.active) l6.flush(outb);
}

// pool1 = max over pool2's 4 completed regions (bit-exact fold; proven).
__global__ void __launch_bounds__(256)
pool1_fold_kernel(float* __restrict__ out) {
    int t = blockIdx.x * blockDim.x + threadIdx.x;
    if (t >= FB * NROI * C4) return;
    int c4 = t & 127;
    int pr = t >> 7;

    float4* base = (float4*)out + ((size_t)pr * NREG) * C4 + c4;
    float4 f0 = base[1 * C4];
    float4 f1 = base[2 * C4];
    float4 f2 = base[3 * C4];
    float4 f3 = base[4 * C4];
    vmax4(f0, f1);
    vmax4(f2, f3);
    vmax4(f0, f2);
    base[0] = f0;
}

extern "C" void kernel_launch(void* const* d_in, const int* in_sizes, int n_in,
                              void* d_out, int out_size) {
    const float* fm   = (const float*)d_in[0];
    const int*   rois = (const int*)d_in[1];
    float*       out  = (float*)d_out;

    int n4 = out_size / 4;                        // whole output as uint4
    prep_kernel<<<(n4 + 255) / 256, 256>>>(rois, (unsigned int*)out);
    roi_pool_l1fused<<<FB * NROI * NCK, 128>>>(fm, out);
    pool1_fold_kernel<<<(FB * NROI * C4 + 255) / 256, 256>>>(out);
}

// round 14
// speedup vs baseline: 3.2193x; 1.6744x over previous
#include <cuda_runtime.h>
#include <math.h>

constexpr int FH   = 96;
constexpr int FW   = 96;
constexpr int FC   = 512;
constexpr int FB   = 16;
constexpr int NROI = 32;
constexpr int NREG = 50;          // 1 + 4 + 9 + 36
constexpr int C4   = FC / 4;      // 128 float4 channels
constexpr int RS   = FW * C4;     // row stride in float4 units
constexpr int CH   = 4;           // rows per chunk
constexpr int NCK  = FH / CH;     // 24

__device__ int4 d_regions[NROI * NREG];

// ---------------------------------------------------------------------------
// Prep: init ALL 50 regions to -inf bits + exact Python-double boundaries
// (verified math, unchanged since R1).
// ---------------------------------------------------------------------------
__global__ void prep_kernel(const int* __restrict__ rois,
                            unsigned int* __restrict__ out) {
    int gid = blockIdx.x * blockDim.x + threadIdx.x;

    if (gid < FB * NROI * NREG * 128) {
        ((uint4*)out)[gid] =
            make_uint4(0xFF800000u, 0xFF800000u, 0xFF800000u, 0xFF800000u);
    }

    if (gid >= NROI * NREG) return;
    int roi = gid / NREG;
    int k   = gid % NREG;

    int P, off;
    if      (k < 1)  { P = 1; off = 0; }
    else if (k < 5)  { P = 2; off = 1; }
    else if (k < 14) { P = 3; off = 5; }
    else             { P = 6; off = 14; }
    int idx = k - off;
    int ix  = idx / P;
    int jy  = idx % P;

    double x = (double)rois[roi * 4 + 0];
    double y = (double)rois[roi * 4 + 1];
    double w = (double)rois[roi * 4 + 2];
    double h = (double)rois[roi * 4 + 3];

    double cl = h / (double)P;   // x-axis step (reference quirk)
    double rl = w / (double)P;   // y-axis step

    double tx = __dadd_rn(x, __dmul_rn((double)ix, cl));
    int x1 = (int)rint(tx);
    int x2 = (int)rint(__dadd_rn(tx, cl));

    double ty = __dadd_rn(y, __dmul_rn((double)jy, rl));
    int y1 = (int)rint(ty);
    int y2 = (int)rint(__dadd_rn(ty, rl));

    x1 = max(0, min(FW, x1));
    x2 = max(0, min(FW, x2));
    y1 = max(0, min(FH, y1));
    y2 = max(0, min(FH, y2));

    d_regions[roi * NREG + k] = make_int4(x1, x2, y1, y2);
}

// Sign-split float atomic max on raw bits (proven rel_err=0 in R6-R13).
// Note: v=-inf is a no-op on any stored value -> flushing untouched accs safe.
__device__ __forceinline__ void atomicMaxFloat(float* addr, float v) {
    if (v >= 0.0f) atomicMax((int*)addr, __float_as_int(v));
    else           atomicMin((unsigned int*)addr, __float_as_uint(v));
}

__device__ __forceinline__ void vmax4(float4& a, const float4 b) {
    a.x = fmaxf(a.x, b.x);
    a.y = fmaxf(a.y, b.y);
    a.z = fmaxf(a.z, b.z);
    a.w = fmaxf(a.w, b.w);
}

__device__ __forceinline__ void atomic4(float* o, const float4 a) {
    atomicMaxFloat(o + 0, a.x);
    atomicMaxFloat(o + 1, a.y);
    atomicMaxFloat(o + 2, a.z);
    atomicMaxFloat(o + 3, a.w);
}

#define NEG4 make_float4(-INFINITY, -INFINITY, -INFINITY, -INFINITY)

// Scan [xa,xb) of a row, feeding 1/2/3 accumulators per loaded value.
__device__ __forceinline__ void scan1(const float4* __restrict__ rowp,
                                      int xa, int xb, float4& t0) {
    int x = xa;
    for (; x + 2 <= xb; x += 2) {
        float4 v0 = __ldg(rowp + (size_t)x * C4);
        float4 v1 = __ldg(rowp + (size_t)(x + 1) * C4);
        vmax4(t0, v0); vmax4(t0, v1);
    }
    if (x < xb) vmax4(t0, __ldg(rowp + (size_t)x * C4));
}
__device__ __forceinline__ void scan2(const float4* __restrict__ rowp,
                                      int xa, int xb, float4& t0, float4& t1) {
    int x = xa;
    for (; x + 2 <= xb; x += 2) {
        float4 v0 = __ldg(rowp + (size_t)x * C4);
        float4 v1 = __ldg(rowp + (size_t)(x + 1) * C4);
        vmax4(t0, v0); vmax4(t1, v0);
        vmax4(t0, v1); vmax4(t1, v1);
    }
    if (x < xb) {
        float4 v0 = __ldg(rowp + (size_t)x * C4);
        vmax4(t0, v0); vmax4(t1, v0);
    }
}
__device__ __forceinline__ void scan3(const float4* __restrict__ rowp,
                                      int xa, int xb,
                                      float4& t0, float4& t1, float4& t2) {
    int x = xa;
    for (; x + 2 <= xb; x += 2) {
        float4 v0 = __ldg(rowp + (size_t)x * C4);
        float4 v1 = __ldg(rowp + (size_t)(x + 1) * C4);
        vmax4(t0, v0); vmax4(t1, v0); vmax4(t2, v0);
        vmax4(t0, v1); vmax4(t1, v1); vmax4(t2, v1);
    }
    if (x < xb) {
        float4 v0 = __ldg(rowp + (size_t)x * C4);
        vmax4(t0, v0); vmax4(t1, v0); vmax4(t2, v0);
    }
}

// ---------------------------------------------------------------------------
// SINGLE-SWEEP kernel: block = (b, roi, 4-row chunk), thread = float4 channel.
// Each loaded value feeds pool6+pool3+pool2 accumulators (max is idempotent,
// overlaps/double-loads harmless). All boundaries are each region's own exact
// values. Only pool6 cut3/band3 can jitter (odd h/w): x-gap scanned
// explicitly for pool3/pool2; y-gap rows skip pool6 (in6); y-overlap rows get
// a rare L1-hot fixup pass into the next pool6 band. pool1 folded from pool2
// flushes (bit-exact, proven since R7).
// ---------------------------------------------------------------------------
__global__ void __launch_bounds__(128)
roi_pool_onesweep(const float* __restrict__ fm, float* __restrict__ out) {
    int bid = blockIdx.x;
    int ck  = bid % NCK;
    int rr  = bid / NCK;
    int roi = rr & 31;
    int b   = rr >> 5;            // batch slowest: co-resident blocks share image
    int c   = threadIdx.x;

    const int4* regs = d_regions + roi * NREG;
    int4 r0 = __ldg(&regs[0]);    // pool1 box = union box, exact
    int row_lo = max(r0.z, ck * CH);
    int row_hi = min(r0.w, ck * CH + CH);
    if (row_lo >= row_hi) return;

    // x-segment bounds (each segment's OWN exact range)
    int s6[6], e6[6];
#pragma unroll
    for (int i = 0; i < 6; i++) { int4 q = __ldg(&regs[14 + i * 6]); s6[i] = q.x; e6[i] = q.y; }
    int s3[3], e3[3];
#pragma unroll
    for (int i = 0; i < 3; i++) { int4 q = __ldg(&regs[5 + i * 3]);  s3[i] = q.x; e3[i] = q.y; }
    int m  = __ldg(&regs[3]).x;   // pool2 x-cut  (region (1,0), exact)
    int ym = __ldg(&regs[2]).z;   // pool2 y-cut  (region (0,1), exact)

    const float4* fmb  = (const float4*)fm + (size_t)b * FH * FW * C4 + c;
    float*        outb = out + (((size_t)(b * NROI + roi) * NREG) << 9) + c * 4;

    float4 a6[6], a3[3], a2[2];
#pragma unroll
    for (int i = 0; i < 6; i++) a6[i] = NEG4;
#pragma unroll
    for (int i = 0; i < 3; i++) a3[i] = NEG4;
    a2[0] = NEG4; a2[1] = NEG4;

    // pool6 band walker (bands may gap/overlap at 2|3 boundary)
    int jb6 = 0, b6y1, b6y2, b6y1n;
    { int4 q = __ldg(&regs[14]); b6y1 = q.z; b6y2 = q.w; }
    while (jb6 < 6 && row_lo >= b6y2) {
        jb6++;
        if (jb6 < 6) { int4 q = __ldg(&regs[14 + jb6]); b6y1 = q.z; b6y2 = q.w; }
    }
    b6y1n = (jb6 + 1 < 6) ? __ldg(&regs[14 + jb6 + 1]).z : (1 << 30);
    if (jb6 >= 6) { b6y1 = 1 << 30; b6y2 = 1 << 30; }

    // pool3 band walker (tiles exactly: every row is in exactly one band)
    int jb3 = 0, b3y2 = __ldg(&regs[5]).w;
    while (jb3 < 3 && row_lo >= b3y2) {
        jb3++;
        if (jb3 < 3) b3y2 = __ldg(&regs[5 + jb3]).w;
    }

    int b2cur = (row_lo >= ym) ? 1 : 0;

    for (int y = row_lo; y < row_hi; y++) {
        // walkers: flush-on-advance (NEG flushes are harmless no-ops)
        while (jb6 < 6 && y >= b6y2) {
#pragma unroll
            for (int i = 0; i < 6; i++) {
                atomic4(outb + ((size_t)(14 + i * 6 + jb6) << 9), a6[i]);
                a6[i] = NEG4;
            }
            jb6++;
            if (jb6 < 6) {
                int4 q = __ldg(&regs[14 + jb6]); b6y1 = q.z; b6y2 = q.w;
                b6y1n = (jb6 + 1 < 6) ? __ldg(&regs[14 + jb6 + 1]).z : (1 << 30);
            } else { b6y1 = 1 << 30; b6y2 = 1 << 30; b6y1n = 1 << 30; }
        }
        while (jb3 < 3 && y >= b3y2) {
#pragma unroll
            for (int i = 0; i < 3; i++) {
                atomic4(outb + ((size_t)(5 + i * 3 + jb3) << 9), a3[i]);
                a3[i] = NEG4;
            }
            jb3++;
            if (jb3 < 3) b3y2 = __ldg(&regs[5 + jb3]).w;
        }
        if (b2cur == 0 && y >= ym) {
#pragma unroll
            for (int i = 0; i < 2; i++) {
                atomic4(outb + ((size_t)(1 + i * 2) << 9), a2[i]);
                atomic4(outb, a2[i]);                 // pool1 fold
                a2[i] = NEG4;
            }
            b2cur = 1;
        }

        const float4* rowp = fmb + (size_t)y * RS;
        bool in6 = (y >= b6y1);                       // (jb6<6 implied by b6y1)

        if (in6) {
            // segs 0,1: entirely in pool3 seg0, pool2 seg0 (cut2 = p3cut1 < m)
            scan3(rowp, s6[0], e6[0], a6[0], a3[0], a2[0]);
            scan3(rowp, s6[1], e6[1], a6[1], a3[0], a2[0]);
            // seg 2 straddles m at most once
            scan3(rowp, s6[2], min(e6[2], m), a6[2], a3[1], a2[0]);
            scan3(rowp, max(s6[2], m), e6[2], a6[2], a3[1], a2[1]);
            // jitter gap between seg2 end / seg3 start (<=1 px, odd h only)
            if (e6[2] < s6[3]) {
                scan2(rowp, e6[2], min(s6[3], m), a3[1], a2[0]);
                scan2(rowp, max(e6[2], m), s6[3], a3[1], a2[1]);
            }
            scan3(rowp, s6[3], min(e6[3], m), a6[3], a3[1], a2[0]);
            scan3(rowp, max(s6[3], m), e6[3], a6[3], a3[1], a2[1]);
            // segs 4,5: entirely in pool3 seg2, pool2 seg1 (cut4 = p3cut2 > m)
            scan3(rowp, s6[4], e6[4], a6[4], a3[2], a2[1]);
            scan3(rowp, s6[5], e6[5], a6[5], a3[2], a2[1]);
        } else {
            // pool6 gap row: pool3 segments tile [x, x+h) exactly
            scan2(rowp, s3[0], e3[0], a3[0], a2[0]);
            scan2(rowp, s3[1], min(e3[1], m), a3[1], a2[0]);
            scan2(rowp, max(s3[1], m), e3[1], a3[1], a2[1]);
            scan2(rowp, s3[2], e3[2], a3[2], a2[1]);
        }

        // y-overlap fixup: row also belongs to pool6 band jb6+1 (rare, L1-hot)
        if (y >= b6y1n) {
#pragma unroll
            for (int i = 0; i < 6; i++) {
                float4 t = NEG4;
                scan1(rowp, s6[i], e6[i], t);
                atomic4(outb + ((size_t)(14 + i * 6 + jb6 + 1) << 9), t);
            }
        }
    }

    // final flushes (NEG-safe)
    if (jb6 < 6) {
#pragma unroll
        for (int i = 0; i < 6; i++)
            atomic4(outb + ((size_t)(14 + i * 6 + jb6) << 9), a6[i]);
    }
    if (jb3 < 3) {
#pragma unroll
        for (int i = 0; i < 3; i++)
            atomic4(outb + ((size_t)(5 + i * 3 + jb3) << 9), a3[i]);
    }
#pragma unroll
    for (int i = 0; i < 2; i++) {
        atomic4(outb + ((size_t)(1 + i * 2 + b2cur) << 9), a2[i]);
        atomic4(outb, a2[i]);                         // pool1 fold
    }
}

extern "C" void kernel_launch(void* const* d_in, const int* in_sizes, int n_in,
                              void* d_out, int out_size) {
    const float* fm   = (const float*)d_in[0];
    const int*   rois = (const int*)d_in[1];
    float*       out  = (float*)d_out;

    int n4 = out_size / 4;                            // whole output as uint4
    prep_kernel<<<(n4 + 255) / 256, 256>>>(rois, (unsigned int*)out);
    roi_pool_onesweep<<<FB * NROI * NCK, 128>>>(fm, out);
}

// round 15
// speedup vs baseline: 3.5712x; 1.1093x over previous
#include <cuda_runtime.h>
#include <math.h>

constexpr int FH   = 96;
constexpr int FW   = 96;
constexpr int FC   = 512;
constexpr int FB   = 16;
constexpr int NROI = 32;
constexpr int NREG = 50;          // 1 + 4 + 9 + 36
constexpr int C4   = FC / 4;      // 128 float4 channels
constexpr int RS   = FW * C4;     // row stride in float4 units
constexpr int CH   = 8;           // rows per chunk
constexpr int NCK  = FH / CH;     // 12
constexpr int YBIG = 1 << 30;

__device__ int4 d_regions[NROI * NREG];

// ---------------------------------------------------------------------------
// Prep: init ALL 50 regions to -inf bits + exact Python-double boundaries
// (verified math, unchanged since R1).
// ---------------------------------------------------------------------------
__global__ void prep_kernel(const int* __restrict__ rois,
                            unsigned int* __restrict__ out) {
    int gid = blockIdx.x * blockDim.x + threadIdx.x;

    if (gid < FB * NROI * NREG * 128) {
        ((uint4*)out)[gid] =
            make_uint4(0xFF800000u, 0xFF800000u, 0xFF800000u, 0xFF800000u);
    }

    if (gid >= NROI * NREG) return;
    int roi = gid / NREG;
    int k   = gid % NREG;

    int P, off;
    if      (k < 1)  { P = 1; off = 0; }
    else if (k < 5)  { P = 2; off = 1; }
    else if (k < 14) { P = 3; off = 5; }
    else             { P = 6; off = 14; }
    int idx = k - off;
    int ix  = idx / P;
    int jy  = idx % P;

    double x = (double)rois[roi * 4 + 0];
    double y = (double)rois[roi * 4 + 1];
    double w = (double)rois[roi * 4 + 2];
    double h = (double)rois[roi * 4 + 3];

    double cl = h / (double)P;   // x-axis step (reference quirk)
    double rl = w / (double)P;   // y-axis step

    double tx = __dadd_rn(x, __dmul_rn((double)ix, cl));
    int x1 = (int)rint(tx);
    int x2 = (int)rint(__dadd_rn(tx, cl));

    double ty = __dadd_rn(y, __dmul_rn((double)jy, rl));
    int y1 = (int)rint(ty);
    int y2 = (int)rint(__dadd_rn(ty, rl));

    x1 = max(0, min(FW, x1));
    x2 = max(0, min(FW, x2));
    y1 = max(0, min(FH, y1));
    y2 = max(0, min(FH, y2));

    d_regions[roi * NREG + k] = make_int4(x1, x2, y1, y2);
}

// Sign-split float atomic max on raw bits (proven rel_err=0 in R6-R14).
__device__ __forceinline__ void atomicMaxFloat(float* addr, float v) {
    if (v >= 0.0f) atomicMax((int*)addr, __float_as_int(v));
    else           atomicMin((unsigned int*)addr, __float_as_uint(v));
}

__device__ __forceinline__ void vmax4(float4& a, const float4 b) {
    a.x = fmaxf(a.x, b.x);
    a.y = fmaxf(a.y, b.y);
    a.z = fmaxf(a.z, b.z);
    a.w = fmaxf(a.w, b.w);
}

__device__ __forceinline__ void atomic4(float* o, const float4 a) {
    atomicMaxFloat(o + 0, a.x);
    atomicMaxFloat(o + 1, a.y);
    atomicMaxFloat(o + 2, a.z);
    atomicMaxFloat(o + 3, a.w);
}

#define NEG4 make_float4(-INFINITY, -INFINITY, -INFINITY, -INFINITY)

// ---------------------------------------------------------------------------
// Dual-row scans: D=true reads rows r0 AND r1 (4 loads in flight), D=false
// only r0. Batch values are tree-combined before feeding targets (max is
// exact & associative -> bit-identical, ~2x fewer FMNMX, shorter acc chains).
// ---------------------------------------------------------------------------
template <bool D>
__device__ __forceinline__ void scanT1(const float4* __restrict__ r0,
                                       const float4* __restrict__ r1,
                                       int xa, int xb, float4& t0) {
    int x = xa;
    for (; x + 2 <= xb; x += 2) {
        float4 v0 = __ldg(r0 + (size_t)x * C4);
        float4 v1 = __ldg(r0 + (size_t)(x + 1) * C4);
        if (D) {
            float4 v2 = __ldg(r1 + (size_t)x * C4);
            float4 v3 = __ldg(r1 + (size_t)(x + 1) * C4);
            vmax4(v0, v2); vmax4(v1, v3);
        }
        vmax4(v0, v1);
        vmax4(t0, v0);
    }
    if (x < xb) {
        float4 v0 = __ldg(r0 + (size_t)x * C4);
        if (D) { float4 v2 = __ldg(r1 + (size_t)x * C4); vmax4(v0, v2); }
        vmax4(t0, v0);
    }
}
template <bool D>
__device__ __forceinline__ void scanT2(const float4* __restrict__ r0,
                                       const float4* __restrict__ r1,
                                       int xa, int xb, float4& t0, float4& t1) {
    int x = xa;
    for (; x + 2 <= xb; x += 2) {
        float4 v0 = __ldg(r0 + (size_t)x * C4);
        float4 v1 = __ldg(r0 + (size_t)(x + 1) * C4);
        if (D) {
            float4 v2 = __ldg(r1 + (size_t)x * C4);
            float4 v3 = __ldg(r1 + (size_t)(x + 1) * C4);
            vmax4(v0, v2); vmax4(v1, v3);
        }
        vmax4(v0, v1);
        vmax4(t0, v0); vmax4(t1, v0);
    }
    if (x < xb) {
        float4 v0 = __ldg(r0 + (size_t)x * C4);
        if (D) { float4 v2 = __ldg(r1 + (size_t)x * C4); vmax4(v0, v2); }
        vmax4(t0, v0); vmax4(t1, v0);
    }
}
template <bool D>
__device__ __forceinline__ void scanT3(const float4* __restrict__ r0,
                                       const float4* __restrict__ r1,
                                       int xa, int xb,
                                       float4& t0, float4& t1, float4& t2) {
    int x = xa;
    for (; x + 2 <= xb; x += 2) {
        float4 v0 = __ldg(r0 + (size_t)x * C4);
        float4 v1 = __ldg(r0 + (size_t)(x + 1) * C4);
        if (D) {
            float4 v2 = __ldg(r1 + (size_t)x * C4);
            float4 v3 = __ldg(r1 + (size_t)(x + 1) * C4);
            vmax4(v0, v2); vmax4(v1, v3);
        }
        vmax4(v0, v1);
        vmax4(t0, v0); vmax4(t1, v0); vmax4(t2, v0);
    }
    if (x < xb) {
        float4 v0 = __ldg(r0 + (size_t)x * C4);
        if (D) { float4 v2 = __ldg(r1 + (size_t)x * C4); vmax4(v0, v2); }
        vmax4(t0, v0); vmax4(t1, v0); vmax4(t2, v0);
    }
}

// Row body (identical region logic to the PASSING R14, just D-templated).
#define ROW_BODY(D)                                                           \
    if (in6) {                                                                \
        scanT3<D>(rp0, rp1, s6[0], e6[0], a6[0], a3[0], a2[0]);               \
        scanT3<D>(rp0, rp1, s6[1], e6[1], a6[1], a3[0], a2[0]);               \
        scanT3<D>(rp0, rp1, s6[2], min(e6[2], m), a6[2], a3[1], a2[0]);       \
        scanT3<D>(rp0, rp1, max(s6[2], m), e6[2], a6[2], a3[1], a2[1]);       \
        if (e6[2] < s6[3]) {                                                  \
            scanT2<D>(rp0, rp1, e6[2], min(s6[3], m), a3[1], a2[0]);          \
            scanT2<D>(rp0, rp1, max(e6[2], m), s6[3], a3[1], a2[1]);          \
        }                                                                     \
        scanT3<D>(rp0, rp1, s6[3], min(e6[3], m), a6[3], a3[1], a2[0]);       \
        scanT3<D>(rp0, rp1, max(s6[3], m), e6[3], a6[3], a3[1], a2[1]);       \
        scanT3<D>(rp0, rp1, s6[4], e6[4], a6[4], a3[2], a2[1]);               \
        scanT3<D>(rp0, rp1, s6[5], e6[5], a6[5], a3[2], a2[1]);               \
    } else {                                                                  \
        scanT2<D>(rp0, rp1, s3[0], e3[0], a3[0], a2[0]);                      \
        scanT2<D>(rp0, rp1, s3[1], min(e3[1], m), a3[1], a2[0]);              \
        scanT2<D>(rp0, rp1, max(s3[1], m), e3[1], a3[1], a2[1]);              \
        scanT2<D>(rp0, rp1, s3[2], e3[2], a3[2], a2[1]);                      \
    }

#define FIX_BODY(D) {                                                         \
        _Pragma("unroll")                                                     \
        for (int i = 0; i < 6; i++) {                                         \
            float4 t = NEG4;                                                  \
            scanT1<D>(rp0, rp1, s6[i], e6[i], t);                             \
            atomic4(outb + ((size_t)(14 + i * 6 + jb6 + 1) << 9), t);         \
        }                                                                     \
    }

// ---------------------------------------------------------------------------
// SINGLE-SWEEP kernel (R14 algorithm) + dual-row fast path.
// ---------------------------------------------------------------------------
__global__ void __launch_bounds__(128)
roi_pool_onesweep(const float* __restrict__ fm, float* __restrict__ out) {
    int bid = blockIdx.x;
    int ck  = bid % NCK;
    int rr  = bid / NCK;
    int roi = rr & 31;
    int b   = rr >> 5;            // batch slowest: co-resident blocks share image
    int c   = threadIdx.x;

    const int4* regs = d_regions + roi * NREG;
    int4 r0 = __ldg(&regs[0]);    // pool1 box = union box, exact
    int row_lo = max(r0.z, ck * CH);
    int row_hi = min(r0.w, ck * CH + CH);
    if (row_lo >= row_hi) return;

    int s6[6], e6[6];
#pragma unroll
    for (int i = 0; i < 6; i++) { int4 q = __ldg(&regs[14 + i * 6]); s6[i] = q.x; e6[i] = q.y; }
    int s3[3], e3[3];
#pragma unroll
    for (int i = 0; i < 3; i++) { int4 q = __ldg(&regs[5 + i * 3]);  s3[i] = q.x; e3[i] = q.y; }
    int m  = __ldg(&regs[3]).x;   // pool2 x-cut  (exact)
    int ym = __ldg(&regs[2]).z;   // pool2 y-cut  (exact)

    const float4* fmb  = (const float4*)fm + (size_t)b * FH * FW * C4 + c;
    float*        outb = out + (((size_t)(b * NROI + roi) * NREG) << 9) + c * 4;

    float4 a6[6], a3[3], a2[2];
#pragma unroll
    for (int i = 0; i < 6; i++) a6[i] = NEG4;
#pragma unroll
    for (int i = 0; i < 3; i++) a3[i] = NEG4;
    a2[0] = NEG4; a2[1] = NEG4;

    // pool6 band walker (only the 2|3 seam can gap/overlap; proven + verified)
    int jb6 = 0, b6y1, b6y2, b6y1n;
    { int4 q = __ldg(&regs[14]); b6y1 = q.z; b6y2 = q.w; }
    while (jb6 < 6 && row_lo >= b6y2) {
        jb6++;
        if (jb6 < 6) { int4 q = __ldg(&regs[14 + jb6]); b6y1 = q.z; b6y2 = q.w; }
    }
    b6y1n = (jb6 + 1 < 6) ? __ldg(&regs[14 + jb6 + 1]).z : YBIG;
    if (jb6 >= 6) { b6y1 = YBIG; b6y2 = YBIG; b6y1n = YBIG; }

    // pool3 band walker (tiles exactly)
    int jb3 = 0, b3y2 = __ldg(&regs[5]).w;
    while (jb3 < 3 && row_lo >= b3y2) {
        jb3++;
        b3y2 = (jb3 < 3) ? __ldg(&regs[5 + jb3]).w : YBIG;
    }

    int b2cur = (row_lo >= ym) ? 1 : 0;

    for (int y = row_lo; y < row_hi; ) {
        // walkers: flush-on-advance (NEG flushes harmless)
        while (jb6 < 6 && y >= b6y2) {
#pragma unroll
            for (int i = 0; i < 6; i++) {
                atomic4(outb + ((size_t)(14 + i * 6 + jb6) << 9), a6[i]);
                a6[i] = NEG4;
            }
            jb6++;
            if (jb6 < 6) {
                int4 q = __ldg(&regs[14 + jb6]); b6y1 = q.z; b6y2 = q.w;
                b6y1n = (jb6 + 1 < 6) ? __ldg(&regs[14 + jb6 + 1]).z : YBIG;
            } else { b6y1 = YBIG; b6y2 = YBIG; b6y1n = YBIG; }
        }
        while (jb3 < 3 && y >= b3y2) {
#pragma unroll
            for (int i = 0; i < 3; i++) {
                atomic4(outb + ((size_t)(5 + i * 3 + jb3) << 9), a3[i]);
                a3[i] = NEG4;
            }
            jb3++;
            b3y2 = (jb3 < 3) ? __ldg(&regs[5 + jb3]).w : YBIG;
        }
        if (b2cur == 0 && y >= ym) {
#pragma unroll
            for (int i = 0; i < 2; i++) {
                atomic4(outb + ((size_t)(1 + i * 2) << 9), a2[i]);
                atomic4(outb, a2[i]);                 // pool1 fold
                a2[i] = NEG4;
            }
            b2cur = 1;
        }

        const float4* rp0 = fmb + (size_t)y * RS;
        const float4* rp1 = rp0 + RS;
        bool in6 = (y >= b6y1);
        bool ov  = (y >= b6y1n);

        // dual-row fast path: y+1 must share the exact same band state
        bool dual = (y + 1 < row_hi) && (y + 1 < b6y2) && (y + 1 < b3y2)
                 && (b2cur == 1 || y + 1 < ym)
                 && (in6 || y + 1 < b6y1)
                 && (ov  || y + 1 < b6y1n);

        if (dual) {
            ROW_BODY(true);
            if (ov) FIX_BODY(true);
            y += 2;
        } else {
            ROW_BODY(false);
            if (ov) FIX_BODY(false);
            y += 1;
        }
    }

    // final flushes (NEG-safe)
    if (jb6 < 6) {
#pragma unroll
        for (int i = 0; i < 6; i++)
            atomic4(outb + ((size_t)(14 + i * 6 + jb6) << 9), a6[i]);
    }
    if (jb3 < 3) {
#pragma unroll
        for (int i = 0; i < 3; i++)
            atomic4(outb + ((size_t)(5 + i * 3 + jb3) << 9), a3[i]);
    }
#pragma unroll
    for (int i = 0; i < 2; i++) {
        atomic4(outb + ((size_t)(1 + i * 2 + b2cur) << 9), a2[i]);
        atomic4(outb, a2[i]);                         // pool1 fold
    }
}

extern "C" void kernel_launch(void* const* d_in, const int* in_sizes, int n_in,
                              void* d_out, int out_size) {
    const float* fm   = (const float*)d_in[0];
    const int*   rois = (const int*)d_in[1];
    float*       out  = (float*)d_out;

    int n4 = out_size / 4;                            // whole output as uint4
    prep_kernel<<<(n4 + 255) / 256, 256>>>(rois, (unsigned int*)out);
    roi_pool_onesweep<<<FB * NROI * NCK, 128>>>(fm, out);
}

// round 16
// speedup vs baseline: 3.9560x; 1.1078x over previous
#include <cuda_runtime.h>
#include <math.h>

constexpr int FH   = 96;
constexpr int FW   = 96;
constexpr int FC   = 512;
constexpr int FB   = 16;
constexpr int NROI = 32;
constexpr int NREG = 50;          // 1 + 4 + 9 + 36
constexpr int C4   = FC / 4;      // 128 float4 channels
constexpr int RS   = FW * C4;     // row stride in float4 units
constexpr int CH   = 8;           // rows per chunk
constexpr int NCK  = FH / CH;     // 12
constexpr int YBIG = 1 << 30;

__device__ int4 d_regions[NROI * NREG];

// ---------------------------------------------------------------------------
// Prep: init ALL 50 regions to -inf bits + exact Python-double boundaries
// (verified math, unchanged since R1).
// ---------------------------------------------------------------------------
__global__ void prep_kernel(const int* __restrict__ rois,
                            unsigned int* __restrict__ out) {
    int gid = blockIdx.x * blockDim.x + threadIdx.x;

    if (gid < FB * NROI * NREG * 128) {
        ((uint4*)out)[gid] =
            make_uint4(0xFF800000u, 0xFF800000u, 0xFF800000u, 0xFF800000u);
    }

    if (gid >= NROI * NREG) return;
    int roi = gid / NREG;
    int k   = gid % NREG;

    int P, off;
    if      (k < 1)  { P = 1; off = 0; }
    else if (k < 5)  { P = 2; off = 1; }
    else if (k < 14) { P = 3; off = 5; }
    else             { P = 6; off = 14; }
    int idx = k - off;
    int ix  = idx / P;
    int jy  = idx % P;

    double x = (double)rois[roi * 4 + 0];
    double y = (double)rois[roi * 4 + 1];
    double w = (double)rois[roi * 4 + 2];
    double h = (double)rois[roi * 4 + 3];

    double cl = h / (double)P;   // x-axis step (reference quirk)
    double rl = w / (double)P;   // y-axis step

    double tx = __dadd_rn(x, __dmul_rn((double)ix, cl));
    int x1 = (int)rint(tx);
    int x2 = (int)rint(__dadd_rn(tx, cl));

    double ty = __dadd_rn(y, __dmul_rn((double)jy, rl));
    int y1 = (int)rint(ty);
    int y2 = (int)rint(__dadd_rn(ty, rl));

    x1 = max(0, min(FW, x1));
    x2 = max(0, min(FW, x2));
    y1 = max(0, min(FH, y1));
    y2 = max(0, min(FH, y2));

    d_regions[roi * NREG + k] = make_int4(x1, x2, y1, y2);
}

// Sign-split float atomic max on raw bits (proven rel_err=0 in R6-R15).
__device__ __forceinline__ void atomicMaxFloat(float* addr, float v) {
    if (v >= 0.0f) atomicMax((int*)addr, __float_as_int(v));
    else           atomicMin((unsigned int*)addr, __float_as_uint(v));
}

__device__ __forceinline__ void vmax4(float4& a, const float4 b) {
    a.x = fmaxf(a.x, b.x);
    a.y = fmaxf(a.y, b.y);
    a.z = fmaxf(a.z, b.z);
    a.w = fmaxf(a.w, b.w);
}

__device__ __forceinline__ void atomic4(float* o, const float4 a) {
    atomicMaxFloat(o + 0, a.x);
    atomicMaxFloat(o + 1, a.y);
    atomicMaxFloat(o + 2, a.z);
    atomicMaxFloat(o + 3, a.w);
}

#define NEG4 make_float4(-INFINITY, -INFINITY, -INFINITY, -INFINITY)

// ---------------------------------------------------------------------------
// Multi-row segment scan: rows rp..rp+(NR-1)*RS, x in [xa,xb), tree-combined
// into t. NR=4 with x-unroll 2 -> 8 independent LDG.128 in flight.
// Exact: max is associative/commutative; combine order irrelevant.
// ---------------------------------------------------------------------------
template <int NR>
__device__ __forceinline__ void scanR(const float4* __restrict__ rp,
                                      int xa, int xb, float4& t) {
    int x = xa;
    for (; x + 2 <= xb; x += 2) {
        const float4* p0 = rp + (size_t)x * C4;
        const float4* p1 = p0 + C4;
        float4 a = __ldg(p0);
        float4 b = __ldg(p1);
        if (NR > 1) {
            float4 c = __ldg(p0 + RS);
            float4 d = __ldg(p1 + RS);
            if (NR > 2) {
                float4 e = __ldg(p0 + 2 * RS);
                float4 f = __ldg(p1 + 2 * RS);
                float4 g = __ldg(p0 + 3 * RS);
                float4 h = __ldg(p1 + 3 * RS);
                vmax4(a, e); vmax4(b, f); vmax4(c, g); vmax4(d, h);
            }
            vmax4(a, c); vmax4(b, d);
        }
        vmax4(a, b);
        vmax4(t, a);
    }
    if (x < xb) {
        const float4* p0 = rp + (size_t)x * C4;
        float4 a = __ldg(p0);
        if (NR > 1) {
            float4 c = __ldg(p0 + RS);
            if (NR > 2) {
                float4 e = __ldg(p0 + 2 * RS);
                float4 g = __ldg(p0 + 3 * RS);
                vmax4(a, e); vmax4(c, g);
            }
            vmax4(a, c);
        }
        vmax4(t, a);
    }
}

// Run body: same exact segment/gap/overlap coverage as PASSING R14/R15,
// with per-segment deferred merge into the 1-3 target accumulators.
#define SEG(NR, xa, xb, ...) do {                                             \
        float4 t = NEG4;                                                      \
        scanR<NR>(rp0, (xa), (xb), t);                                        \
        __VA_ARGS__;                                                          \
    } while (0)

#define RUN_BODY(NR) do {                                                     \
    if (in6) {                                                                \
        SEG(NR, s6[0], e6[0],        vmax4(a6[0],t); vmax4(a3[0],t); vmax4(a2[0],t)); \
        SEG(NR, s6[1], e6[1],        vmax4(a6[1],t); vmax4(a3[0],t); vmax4(a2[0],t)); \
        SEG(NR, s6[2], min(e6[2],m), vmax4(a6[2],t); vmax4(a3[1],t); vmax4(a2[0],t)); \
        SEG(NR, max(s6[2],m), e6[2], vmax4(a6[2],t); vmax4(a3[1],t); vmax4(a2[1],t)); \
        if (e6[2] < s6[3]) {                                                  \
            SEG(NR, e6[2], min(s6[3],m), vmax4(a3[1],t); vmax4(a2[0],t));     \
            SEG(NR, max(e6[2],m), s6[3], vmax4(a3[1],t); vmax4(a2[1],t));     \
        }                                                                     \
        SEG(NR, s6[3], min(e6[3],m), vmax4(a6[3],t); vmax4(a3[1],t); vmax4(a2[0],t)); \
        SEG(NR, max(s6[3],m), e6[3], vmax4(a6[3],t); vmax4(a3[1],t); vmax4(a2[1],t)); \
        SEG(NR, s6[4], e6[4],        vmax4(a6[4],t); vmax4(a3[2],t); vmax4(a2[1],t)); \
        SEG(NR, s6[5], e6[5],        vmax4(a6[5],t); vmax4(a3[2],t); vmax4(a2[1],t)); \
        if (ov) {                                                             \
            _Pragma("unroll")                                                 \
            for (int i = 0; i < 6; i++) {                                     \
                float4 t2 = NEG4;                                             \
                scanR<NR>(rp0, s6[i], e6[i], t2);                             \
                atomic4(outb + ((size_t)(14 + i * 6 + jb6 + 1) << 9), t2);    \
            }                                                                 \
        }                                                                     \
    } else {                                                                  \
        SEG(NR, s3[0], e3[0],        vmax4(a3[0],t); vmax4(a2[0],t));         \
        SEG(NR, s3[1], min(e3[1],m), vmax4(a3[1],t); vmax4(a2[0],t));         \
        SEG(NR, max(s3[1],m), e3[1], vmax4(a3[1],t); vmax4(a2[1],t));         \
        SEG(NR, s3[2], e3[2],        vmax4(a3[2],t); vmax4(a2[1],t));         \
    }                                                                         \
} while (0)

// ---------------------------------------------------------------------------
// SINGLE-SWEEP kernel (R14/R15 algorithm) + run-length multi-row dispatch.
// ---------------------------------------------------------------------------
__global__ void __launch_bounds__(128)
roi_pool_onesweep(const float* __restrict__ fm, float* __restrict__ out) {
    int bid = blockIdx.x;
    int ck  = bid % NCK;
    int rr  = bid / NCK;
    int roi = rr & 31;
    int b   = rr >> 5;            // batch slowest: co-resident blocks share image
    int c   = threadIdx.x;

    const int4* regs = d_regions + roi * NREG;
    int4 r0 = __ldg(&regs[0]);    // pool1 box = union box, exact
    int row_lo = max(r0.z, ck * CH);
    int row_hi = min(r0.w, ck * CH + CH);
    if (row_lo >= row_hi) return;

    int s6[6], e6[6];
#pragma unroll
    for (int i = 0; i < 6; i++) { int4 q = __ldg(&regs[14 + i * 6]); s6[i] = q.x; e6[i] = q.y; }
    int s3[3], e3[3];
#pragma unroll
    for (int i = 0; i < 3; i++) { int4 q = __ldg(&regs[5 + i * 3]);  s3[i] = q.x; e3[i] = q.y; }
    int m  = __ldg(&regs[3]).x;   // pool2 x-cut  (exact)
    int ym = __ldg(&regs[2]).z;   // pool2 y-cut  (exact)

    const float4* fmb  = (const float4*)fm + (size_t)b * FH * FW * C4 + c;
    float*        outb = out + (((size_t)(b * NROI + roi) * NREG) << 9) + c * 4;

    float4 a6[6], a3[3], a2[2];
#pragma unroll
    for (int i = 0; i < 6; i++) a6[i] = NEG4;
#pragma unroll
    for (int i = 0; i < 3; i++) a3[i] = NEG4;
    a2[0] = NEG4; a2[1] = NEG4;

    // pool6 band walker (only the 2|3 seam can gap/overlap; verified)
    int jb6 = 0, b6y1, b6y2, b6y1n;
    { int4 q = __ldg(&regs[14]); b6y1 = q.z; b6y2 = q.w; }
    while (jb6 < 6 && row_lo >= b6y2) {
        jb6++;
        if (jb6 < 6) { int4 q = __ldg(&regs[14 + jb6]); b6y1 = q.z; b6y2 = q.w; }
    }
    b6y1n = (jb6 + 1 < 6) ? __ldg(&regs[14 + jb6 + 1]).z : YBIG;
    if (jb6 >= 6) { b6y1 = YBIG; b6y2 = YBIG; b6y1n = YBIG; }

    // pool3 band walker (tiles exactly on this data; verified rel_err=0)
    int jb3 = 0, b3y2 = __ldg(&regs[5]).w;
    while (jb3 < 3 && row_lo >= b3y2) {
        jb3++;
        b3y2 = (jb3 < 3) ? __ldg(&regs[5 + jb3]).w : YBIG;
    }

    int b2cur = (row_lo >= ym) ? 1 : 0;

    for (int y = row_lo; y < row_hi; ) {
        // walkers: flush-on-advance (NEG flushes harmless)
        while (jb6 < 6 && y >= b6y2) {
#pragma unroll
            for (int i = 0; i < 6; i++) {
                atomic4(outb + ((size_t)(14 + i * 6 + jb6) << 9), a6[i]);
                a6[i] = NEG4;
            }
            jb6++;
            if (jb6 < 6) {
                int4 q = __ldg(&regs[14 + jb6]); b6y1 = q.z; b6y2 = q.w;
                b6y1n = (jb6 + 1 < 6) ? __ldg(&regs[14 + jb6 + 1]).z : YBIG;
            } else { b6y1 = YBIG; b6y2 = YBIG; b6y1n = YBIG; }
        }
        while (jb3 < 3 && y >= b3y2) {
#pragma unroll
            for (int i = 0; i < 3; i++) {
                atomic4(outb + ((size_t)(5 + i * 3 + jb3) << 9), a3[i]);
                a3[i] = NEG4;
            }
            jb3++;
            b3y2 = (jb3 < 3) ? __ldg(&regs[5 + jb3]).w : YBIG;
        }
        if (b2cur == 0 && y >= ym) {
#pragma unroll
            for (int i = 0; i < 2; i++) {
                atomic4(outb + ((size_t)(1 + i * 2) << 9), a2[i]);
                atomic4(outb, a2[i]);                 // pool1 fold
                a2[i] = NEG4;
            }
            b2cur = 1;
        }

        // run of rows with constant band state
        int ynext = min(min(row_hi, b6y2), b3y2);
        if (y < ym)    ynext = min(ynext, ym);
        if (y < b6y1)  ynext = min(ynext, b6y1);
        if (y < b6y1n) ynext = min(ynext, b6y1n);

        bool in6 = (y >= b6y1);
        bool ov  = (y >= b6y1n);
        const float4* rp0 = fmb + (size_t)y * RS;
        int L = ynext - y;

        if (L >= 4)      { RUN_BODY(4); y += 4; }
        else if (L >= 2) { RUN_BODY(2); y += 2; }
        else             { RUN_BODY(1); y += 1; }
    }

    // final flushes (NEG-safe)
    if (jb6 < 6) {
#pragma unroll
        for (int i = 0; i < 6; i++)
            atomic4(outb + ((size_t)(14 + i * 6 + jb6) << 9), a6[i]);
    }
    if (jb3 < 3) {
#pragma unroll
        for (int i = 0; i < 3; i++)
            atomic4(outb + ((size_t)(5 + i * 3 + jb3) << 9), a3[i]);
    }
#pragma unroll
    for (int i = 0; i < 2; i++) {
        atomic4(outb + ((size_t)(1 + i * 2 + b2cur) << 9), a2[i]);
        atomic4(outb, a2[i]);                         // pool1 fold
    }
}

extern "C" void kernel_launch(void* const* d_in, const int* in_sizes, int n_in,
                              void* d_out, int out_size) {
    const float* fm   = (const float*)d_in[0];
    const int*   rois = (const int*)d_in[1];
    float*       out  = (float*)d_out;

    int n4 = out_size / 4;                            // whole output as uint4
    prep_kernel<<<(n4 + 255) / 256, 256>>>(rois, (unsigned int*)out);
    roi_pool_onesweep<<<FB * NROI * NCK, 128>>>(fm, out);
}